// round 12
// baseline (speedup 1.0000x reference)
#include <cuda_runtime.h>
#include <math.h>

#define SRC_LEN 400
#define TGT_LEN 100
#define Bsz     32
#define Ed      256
#define Hd      512
#define Vd      32000
#define G3H     1536
#define NB      64       // recurrence grid: 64 blocks x 8 j-rows
#define NCH     125      // logits v-chunks of 256
#define TQ      4        // timesteps per logits block
#define TGROUPS (TGT_LEN / TQ)   // 25
#define RTHR    512

// ---------------- device scratch --------------------------------------------
__device__ float  g_gi_enc[(size_t)SRC_LEN * G3H * Bsz];
__device__ float  g_gi_dec[(size_t)TGT_LEN * G3H * Bsz];
__device__ float2 g_h2[2][(Hd / 2) * Bsz];
__device__ float2 g_hall[(size_t)TGT_LEN * (Hd / 2) * Bsz];
__device__ float2 g_oeall[(size_t)TGT_LEN * (Ed / 2) * Bsz];
__device__ float  g_pm[(size_t)TGT_LEN * NCH * Bsz];
__device__ float  g_ps[(size_t)TGT_LEN * NCH * Bsz];
__device__ int    g_pi[(size_t)TGT_LEN * NCH * Bsz];
__device__ float  g_loss_t[TGT_LEN];
__device__ unsigned g_bar_enc;
__device__ unsigned g_bar_dec;

// ---------------- f32x2 packed FMA ------------------------------------------
__device__ __forceinline__ float2 ffma2(float2 a, float2 b, float2 c) {
    unsigned long long A = *reinterpret_cast<unsigned long long*>(&a);
    unsigned long long B = *reinterpret_cast<unsigned long long*>(&b);
    unsigned long long C = *reinterpret_cast<unsigned long long*>(&c);
    unsigned long long D;
    asm("fma.rn.f32x2 %0, %1, %2, %3;" : "=l"(D) : "l"(A), "l"(B), "l"(C));
    return *reinterpret_cast<float2*>(&D);
}

// ---------------- grid-wide barrier (single counter — measured best) ---------
__device__ __forceinline__ void grid_bar(unsigned* bar, unsigned& target) {
    __syncthreads();
    if (threadIdx.x == 0) {
        target += NB;
        asm volatile("red.release.gpu.global.add.u32 [%0], %1;"
                     :: "l"(bar), "r"(1u) : "memory");
        unsigned v;
        do {
            asm volatile("ld.acquire.gpu.global.u32 %0, [%1];"
                         : "=r"(v) : "l"(bar) : "memory");
        } while (v < target);
    }
    __syncthreads();
}

__global__ void init_kernel() {
    int i = blockIdx.x * blockDim.x + threadIdx.x;
    if (i < Hd * Bsz) ((float*)g_h2[0])[i] = 0.0f;   // encoder h0 = 0
    if (i == 0) { g_bar_enc = 0u; g_bar_dec = 0u; }
}

// ---------------- gi precompute ----------------------------------------------
__global__ void gi_kernel(const int* __restrict__ toks,
                          const float* __restrict__ emb,
                          const float* __restrict__ Wih,
                          const float* __restrict__ bih,
                          int dec_mode) {
    __shared__ float2 xs2[(Ed / 2) * Bsz];
    __shared__ int    tk[Bsz];
    const int t = blockIdx.x, tid = threadIdx.x;

    if (tid < Bsz) {
        int tok;
        if (dec_mode) tok = (t == 0) ? 1 : toks[(t - 1) * Bsz + tid];
        else          tok = toks[t * Bsz + tid];
        tk[tid] = tok;
    }
    __syncthreads();
    {
        const int b = tid & 31, chunk = tid >> 5;
        const float* erow = emb + (size_t)tk[b] * Ed;
        #pragma unroll
        for (int c = 0; c < 8; c++) {
            int e0 = chunk * 32 + c * 4;
            float4 v = *(const float4*)(erow + e0);
            xs2[(e0 >> 1) * Bsz + b]       = make_float2(v.x, v.y);
            xs2[((e0 >> 1) + 1) * Bsz + b] = make_float2(v.z, v.w);
        }
    }
    __syncthreads();

    const int wid = tid >> 5, lane = tid & 31;
    float* out_t = (dec_mode ? g_gi_dec : g_gi_enc) + (size_t)t * G3H * Bsz;

    for (int jt = 0; jt < 24; jt++) {
        const int j0 = wid * 192 + jt * 8;
        float2 acc[8];
        #pragma unroll
        for (int i = 0; i < 8; i++) acc[i] = make_float2(0.f, 0.f);
        #pragma unroll 2
        for (int e = 0; e < Ed; e += 4) {
            const int e2 = e >> 1;
            float2 x01 = xs2[e2 * Bsz + lane];
            float2 x23 = xs2[(e2 + 1) * Bsz + lane];
            const float* wp = Wih + (size_t)j0 * Ed + e;
            #pragma unroll
            for (int jj = 0; jj < 8; jj++) {
                float4 w = *(const float4*)(wp + (size_t)jj * Ed);
                acc[jj] = ffma2(make_float2(w.x, w.y), x01, acc[jj]);
                acc[jj] = ffma2(make_float2(w.z, w.w), x23, acc[jj]);
            }
        }
        #pragma unroll
        for (int jj = 0; jj < 8; jj++)
            out_t[(size_t)(j0 + jj) * Bsz + lane] = acc[jj].x + acc[jj].y + bih[j0 + jj];
    }
}

// ---------------- persistent GRU: 64 blocks x 8 j-rows ------------------------
// smem: ws[24][512] (48KB) + pp[16][12][32] (24KB) = 72KB
#define WS_F   0
#define PP_F   (24 * 512)
#define REC_SMEM_BYTES ((24 * 512 + 16 * 12 * 32) * 4)

__device__ __forceinline__ void load_ws(float* ws, const float* __restrict__ Whh, int j0) {
    for (int i = threadIdx.x; i < 24 * 128; i += RTHR) {
        int r = i >> 7, k4 = i & 127;          // r = g*8 + jl
        int g = r >> 3, jl = r & 7;
        ((float4*)ws)[r * 128 + k4] =
            *(const float4*)&Whh[((size_t)(g * Hd + j0 + jl)) * Hd + k4 * 4];
    }
}

// one GRU step. hprev/hout: GLOBAL h layout [k/2][b] float2. block owns 8 j-rows.
// warp w: rg = w&1 (gate-rows [rg*12, rg*12+12)), ks = w>>1 (64-k slice).
__device__ __forceinline__ void hh_step(const float* __restrict__ ws,
                                        const float2* __restrict__ hprev,
                                        const float* __restrict__ gi_t,
                                        const float* __restrict__ bhh,
                                        float2* __restrict__ hout,
                                        float* __restrict__ pp,
                                        int j0) {
    const int tid = threadIdx.x, wid = tid >> 5, lane = tid & 31;
    const int rg = wid & 1, ks = wid >> 1;

    // epilogue warps (0-3) prefetch gate inputs + old h early (hidden by k-loop)
    float pg[6];
    float2 hold = make_float2(0.f, 0.f);
    if (wid < 4) {
        const int j = j0 + 2 * wid;
        pg[0] = __ldcg(&gi_t[(size_t)(0 * Hd + j) * Bsz + lane]);
        pg[1] = __ldcg(&gi_t[(size_t)(0 * Hd + j + 1) * Bsz + lane]);
        pg[2] = __ldcg(&gi_t[(size_t)(1 * Hd + j) * Bsz + lane]);
        pg[3] = __ldcg(&gi_t[(size_t)(1 * Hd + j + 1) * Bsz + lane]);
        pg[4] = __ldcg(&gi_t[(size_t)(2 * Hd + j) * Bsz + lane]);
        pg[5] = __ldcg(&gi_t[(size_t)(2 * Hd + j + 1) * Bsz + lane]);
        hold  = __ldcg(&hprev[(j0 / 2 + wid) * Bsz + lane]);
    }

    float2 acc[12];
    #pragma unroll
    for (int i = 0; i < 12; i++) acc[i] = make_float2(0.f, 0.f);

    const int kbeg = ks * 64;                  // each warp: 64-k slice
    #pragma unroll 8
    for (int k = kbeg; k < kbeg + 64; k += 4) {
        const int k2 = k >> 1;
        float2 x01 = __ldcg(&hprev[k2 * Bsz + lane]);
        float2 x23 = __ldcg(&hprev[(k2 + 1) * Bsz + lane]);
        #pragma unroll
        for (int i = 0; i < 12; i++) {
            float4 w = *(const float4*)&ws[(rg * 12 + i) * Hd + k];
            acc[i] = ffma2(make_float2(w.x, w.y), x01, acc[i]);
            acc[i] = ffma2(make_float2(w.z, w.w), x23, acc[i]);
        }
    }
    #pragma unroll
    for (int i = 0; i < 12; i++)
        pp[((ks * 2 + rg) * 12 + i) * 32 + lane] = acc[i].x + acc[i].y;
    __syncthreads();

    if (wid < 4) {
        const int fp = wid;
        float s[6];
        #pragma unroll
        for (int g = 0; g < 3; g++) {
            #pragma unroll
            for (int jj = 0; jj < 2; jj++) {
                const int R = g * 8 + 2 * fp + jj;     // gate-row in [0,24)
                const int rg2 = R / 12, ii = R % 12;
                float v = 0.f;
                #pragma unroll
                for (int q = 0; q < 8; q++)
                    v += pp[((q * 2 + rg2) * 12 + ii) * 32 + lane];
                s[g * 2 + jj] = v;
            }
        }
        float hn[2];
        #pragma unroll
        for (int jj = 0; jj < 2; jj++) {
            int j = j0 + 2 * fp + jj;
            float ghr = s[0 + jj] + bhh[j];
            float ghz = s[2 + jj] + bhh[Hd + j];
            float ghn = s[4 + jj] + bhh[2 * Hd + j];
            float r = 1.0f / (1.0f + expf(-(pg[0 + jj] + ghr)));
            float z = 1.0f / (1.0f + expf(-(pg[2 + jj] + ghz)));
            float n = tanhf(pg[4 + jj] + r * ghn);
            float ho = jj ? hold.y : hold.x;
            hn[jj] = (1.0f - z) * n + z * ho;
        }
        __stcg(&hout[(j0 / 2 + fp) * Bsz + lane], make_float2(hn[0], hn[1]));
    }
}

__global__ void __launch_bounds__(RTHR, 1)
enc_persist(const float* __restrict__ Whh, const float* __restrict__ bhh) {
    extern __shared__ float sm[];
    float* ws = sm + WS_F;
    float* pp = sm + PP_F;
    const int j0 = blockIdx.x * 8;

    load_ws(ws, Whh, j0);
    __syncthreads();

    unsigned tgt = 0;
    for (int t = 0; t < SRC_LEN; t++) {
        const float2* hprev = g_h2[t & 1];
        float2* hnew = g_h2[(t & 1) ^ 1];
        hh_step(ws, hprev, g_gi_enc + (size_t)t * G3H * Bsz, bhh, hnew, pp, j0);
        grid_bar(&g_bar_enc, tgt);
    }
    // SRC_LEN=400 even -> final h in g_h2[0]
}

__global__ void __launch_bounds__(RTHR, 1)
dec_rec(const float* __restrict__ Whh, const float* __restrict__ bhh) {
    extern __shared__ float sm[];
    float* ws = sm + WS_F;
    float* pp = sm + PP_F;
    const int j0 = blockIdx.x * 8;

    load_ws(ws, Whh, j0);
    __syncthreads();

    unsigned tc = 0;
    for (int t = 0; t < TGT_LEN; t++) {
        const float2* hprev = (t == 0) ? g_h2[0]
                                       : &g_hall[(size_t)(t - 1) * (Hd / 2) * Bsz];
        hh_step(ws, hprev, g_gi_dec + (size_t)t * G3H * Bsz, bhh,
                &g_hall[(size_t)t * (Hd / 2) * Bsz], pp, j0);
        grid_bar(&g_bar_dec, tc);
    }
}

// ---------------- decoder phase B: batched pre (oe_all) -----------------------
__global__ void __launch_bounds__(256)
pre_all(const float* __restrict__ preW, const float* __restrict__ preb) {
    extern __shared__ float sm[];
    float2* hs = (float2*)sm;     // 64KB
    const int t = blockIdx.x, tid = threadIdx.x;
    {
        const float4* s4 = (const float4*)&g_hall[(size_t)t * (Hd / 2) * Bsz];
        float4* d4 = (float4*)hs;
        for (int i = tid; i < (Hd * Bsz) / 4; i += 256) d4[i] = __ldg(s4 + i);
        __syncthreads();
    }
    const int wid = tid >> 5, lane = tid & 31;
    for (int grp = 0; grp < 4; grp++) {
        const int e0 = wid * 32 + grp * 8;
        float2 acc[8];
        #pragma unroll
        for (int i = 0; i < 8; i++) acc[i] = make_float2(0.f, 0.f);
        const float* wp = preW + (size_t)e0 * Hd;
        #pragma unroll 2
        for (int k = 0; k < Hd; k += 4) {
            const int k2 = k >> 1;
            float2 x01 = hs[k2 * Bsz + lane];
            float2 x23 = hs[(k2 + 1) * Bsz + lane];
            #pragma unroll
            for (int r = 0; r < 8; r++) {
                float4 w = *(const float4*)(wp + (size_t)r * Hd + k);
                acc[r] = ffma2(make_float2(w.x, w.y), x01, acc[r]);
                acc[r] = ffma2(make_float2(w.z, w.w), x23, acc[r]);
            }
        }
        #pragma unroll
        for (int i = 0; i < 4; i++) {
            float v0 = acc[2 * i].x     + acc[2 * i].y     + preb[e0 + 2 * i];
            float v1 = acc[2 * i + 1].x + acc[2 * i + 1].y + preb[e0 + 2 * i + 1];
            g_oeall[((size_t)t * (Ed / 2) + (e0 >> 1) + i) * Bsz + lane] =
                make_float2(v0, v1);
        }
    }
}

// ---------------- decoder phase C: batched logits, 4 timesteps/block ----------
#define LG_SMEM_F (4 * (Ed / 2) * Bsz * 2 + 3 * (TQ * 8 * 32))
__global__ void __launch_bounds__(256, 1)
logits_all(const float* __restrict__ emb, const float* __restrict__ outb) {
    extern __shared__ float sm[];
    float2* oes = (float2*)sm;
    float*  mm  = sm + 4 * (Ed / 2) * Bsz * 2;
    float*  ms  = mm + TQ * 8 * 32;
    int*    mi  = (int*)(ms + TQ * 8 * 32);

    const int bid = blockIdx.x;
    const int c = bid / TGROUPS, grp = bid % TGROUPS;
    const int t0 = grp * TQ;
    const int tid = threadIdx.x, wid = tid >> 5, lane = tid & 31;

    {
        const float4* s4 = (const float4*)&g_oeall[(size_t)t0 * (Ed / 2) * Bsz];
        float4* d4 = (float4*)oes;
        for (int i = tid; i < 4 * (Ed * Bsz) / 4; i += 256) d4[i] = __ldg(s4 + i);
        __syncthreads();
    }

    const int base = c * 256 + wid * 32;
    float m[TQ], s[TQ]; int bi[TQ];
    #pragma unroll
    for (int t = 0; t < TQ; t++) { m[t] = -INFINITY; s[t] = 0.f; bi[t] = 0; }

    for (int vt = 0; vt < 4; vt++) {
        const int vb = base + vt * 8;
        float2 acc[TQ][8];
        #pragma unroll
        for (int t = 0; t < TQ; t++)
            #pragma unroll
            for (int i = 0; i < 8; i++) acc[t][i] = make_float2(0.f, 0.f);
        const float* ep = emb + (size_t)vb * Ed;

        for (int e = 0; e < Ed; e += 4) {
            const int e2 = e >> 1;
            float2 x01[TQ], x23[TQ];
            #pragma unroll
            for (int t = 0; t < TQ; t++) {
                x01[t] = oes[t * (Ed / 2) * Bsz + e2 * Bsz + lane];
                x23[t] = oes[t * (Ed / 2) * Bsz + (e2 + 1) * Bsz + lane];
            }
            #pragma unroll
            for (int vv = 0; vv < 8; vv++) {
                float4 w = *(const float4*)(ep + (size_t)vv * Ed + e);
                float2 w01 = make_float2(w.x, w.y), w23 = make_float2(w.z, w.w);
                #pragma unroll
                for (int t = 0; t < TQ; t++) {
                    acc[t][vv] = ffma2(w01, x01[t], acc[t][vv]);
                    acc[t][vv] = ffma2(w23, x23[t], acc[t][vv]);
                }
            }
        }
        #pragma unroll
        for (int vv = 0; vv < 8; vv++) {
            float lb = outb[vb + vv];
            #pragma unroll
            for (int t = 0; t < TQ; t++) {
                float l = acc[t][vv].x + acc[t][vv].y + lb;
                if (l > m[t]) { s[t] = s[t] * __expf(m[t] - l) + 1.0f; m[t] = l; bi[t] = vb + vv; }
                else          { s[t] += __expf(l - m[t]); }
            }
        }
    }
    #pragma unroll
    for (int t = 0; t < TQ; t++) {
        mm[(t * 8 + wid) * 32 + lane] = m[t];
        ms[(t * 8 + wid) * 32 + lane] = s[t];
        mi[(t * 8 + wid) * 32 + lane] = bi[t];
    }
    __syncthreads();

    if (wid < TQ) {
        const int tt = wid;
        float M = mm[(tt * 8 + 0) * 32 + lane];
        float S = ms[(tt * 8 + 0) * 32 + lane];
        int   I = mi[(tt * 8 + 0) * 32 + lane];
        #pragma unroll
        for (int w = 1; w < 8; w++) {
            float m2 = mm[(tt * 8 + w) * 32 + lane];
            float s2 = ms[(tt * 8 + w) * 32 + lane];
            int   i2 = mi[(tt * 8 + w) * 32 + lane];
            if (m2 > M) { S = S * __expf(M - m2) + s2; I = i2; M = m2; }
            else        { S += s2 * __expf(m2 - M); }
        }
        const size_t idx = ((size_t)(t0 + tt) * NCH + c) * 32 + lane;
        g_pm[idx] = M; g_ps[idx] = S; g_pi[idx] = I;
    }
}

// ---------------- decoder phase D: per-t merge, tokens, loss ------------------
__global__ void __launch_bounds__(256)
merge_all(const int* __restrict__ tgt, const float* __restrict__ emb,
          const float* __restrict__ outb, float* __restrict__ dout) {
    __shared__ float smm[8 * 32], sms[8 * 32];
    __shared__ int   smi[8 * 32];
    const int t = blockIdx.x, tid = threadIdx.x, b = tid & 31, cg = tid >> 5;

    float m = -INFINITY, s = 0.f; int bi = 0;
    const int cb = cg * 16, ce = (cb + 16 < NCH) ? cb + 16 : NCH;
    for (int c = cb; c < ce; c++) {
        const size_t idx = ((size_t)t * NCH + c) * 32 + b;
        float m2 = g_pm[idx], s2 = g_ps[idx];
        int   i2 = g_pi[idx];
        if (m2 > m) { s = s * __expf(m - m2) + s2; bi = i2; m = m2; }
        else        { s += s2 * __expf(m2 - m); }
    }
    smm[cg * 32 + b] = m; sms[cg * 32 + b] = s; smi[cg * 32 + b] = bi;
    __syncthreads();

    if (tid < 32) {
        m = smm[tid]; s = sms[tid]; bi = smi[tid];
        #pragma unroll
        for (int c2 = 1; c2 < 8; c2++) {
            float m2 = smm[c2 * 32 + tid];
            float s2 = sms[c2 * 32 + tid];
            int   i2 = smi[c2 * 32 + tid];
            if (m2 > m) { s = s * __expf(m - m2) + s2; bi = i2; m = m2; }
            else        { s += s2 * __expf(m2 - m); }
        }
        int gold = tgt[t * Bsz + tid];
        float2 acc = make_float2(0.f, 0.f);
        const float* grow = emb + (size_t)gold * Ed;
        #pragma unroll 4
        for (int e = 0; e < Ed; e += 4) {
            float4 w = *(const float4*)(grow + e);
            float2 o01 = g_oeall[((size_t)t * (Ed / 2) + (e >> 1)) * Bsz + tid];
            float2 o23 = g_oeall[((size_t)t * (Ed / 2) + (e >> 1) + 1) * Bsz + tid];
            acc = ffma2(make_float2(w.x, w.y), o01, acc);
            acc = ffma2(make_float2(w.z, w.w), o23, acc);
        }
        float lg = acc.x + acc.y + outb[gold];
        float prob = expf(lg - m) / s;
        float nll = -logf(prob + 1e-20f);
        float maskf = (gold != 0) ? 1.0f : 0.0f;
        float num = nll * maskf, den = maskf;
        #pragma unroll
        for (int o = 16; o > 0; o >>= 1) {
            num += __shfl_down_sync(0xffffffffu, num, o);
            den += __shfl_down_sync(0xffffffffu, den, o);
        }
        dout[t * Bsz + tid] = (float)bi;
        if (tid == 0) g_loss_t[t] = num / fmaxf(den, 1.0f);
    }
}

__global__ void loss_fin(float* __restrict__ dout, int out_size) {
    if (out_size <= TGT_LEN * Bsz) return;
    const int lane = threadIdx.x;
    float s = 0.f;
    for (int t = lane; t < TGT_LEN; t += 32) s += g_loss_t[t];
    #pragma unroll
    for (int o = 16; o > 0; o >>= 1) s += __shfl_down_sync(0xffffffffu, s, o);
    if (lane == 0) dout[TGT_LEN * Bsz] = s;
}

// ---------------- launch ------------------------------------------------------
extern "C" void kernel_launch(void* const* d_in, const int* in_sizes, int n_in,
                              void* d_out, int out_size) {
    const int*   src  = (const int*)  d_in[0];
    const int*   tgt  = (const int*)  d_in[1];
    const float* emb  = (const float*)d_in[2];
    const float* eWih = (const float*)d_in[3];
    const float* eWhh = (const float*)d_in[4];
    const float* ebih = (const float*)d_in[5];
    const float* ebhh = (const float*)d_in[6];
    const float* dWih = (const float*)d_in[7];
    const float* dWhh = (const float*)d_in[8];
    const float* dbih = (const float*)d_in[9];
    const float* dbhh = (const float*)d_in[10];
    const float* preW = (const float*)d_in[11];
    const float* preb = (const float*)d_in[12];
    const float* outb = (const float*)d_in[13];
    float* out = (float*)d_out;

    static int attr_done = 0;
    if (!attr_done) {
        cudaFuncSetAttribute(enc_persist, cudaFuncAttributeMaxDynamicSharedMemorySize,
                             REC_SMEM_BYTES);
        cudaFuncSetAttribute(dec_rec, cudaFuncAttributeMaxDynamicSharedMemorySize,
                             REC_SMEM_BYTES);
        cudaFuncSetAttribute(pre_all, cudaFuncAttributeMaxDynamicSharedMemorySize,
                             65536);
        cudaFuncSetAttribute(logits_all, cudaFuncAttributeMaxDynamicSharedMemorySize,
                             LG_SMEM_F * 4);
        attr_done = 1;
    }

    init_kernel<<<64, 256>>>();
    gi_kernel<<<SRC_LEN, 256>>>(src, emb, eWih, ebih, 0);
    gi_kernel<<<TGT_LEN, 256>>>(tgt, emb, dWih, dbih, 1);
    enc_persist<<<NB, RTHR, REC_SMEM_BYTES>>>(eWhh, ebhh);
    dec_rec<<<NB, RTHR, REC_SMEM_BYTES>>>(dWhh, dbhh);
    pre_all<<<TGT_LEN, 256, 65536>>>(preW, preb);
    logits_all<<<NCH * TGROUPS, 256, LG_SMEM_F * 4>>>(emb, outb);
    merge_all<<<TGT_LEN, 256>>>(tgt, emb, outb, out);
    loss_fin<<<1, 32>>>(out, out_size);
}

// round 13
// speedup vs baseline: 1.2988x; 1.2988x over previous
#include <cuda_runtime.h>
#include <math.h>

#define SRC_LEN 400
#define TGT_LEN 100
#define Bsz     32
#define Ed      256
#define Hd      512
#define Vd      32000
#define G3H     1536
#define NB      128      // persistent grid size (<= 148 SMs -> co-resident)
#define TQ      4        // timesteps per logits block
#define TGROUPS (TGT_LEN / TQ)   // 25
#define LCH     512      // v per logits block (16 warps x 32)
#define NCHB    63       // ceil(32000/512): 62 full + 1 half chunk
#define RTHR    512

// ---------------- device scratch --------------------------------------------
__device__ float  g_gi_enc[(size_t)SRC_LEN * G3H * Bsz];
__device__ float  g_gi_dec[(size_t)TGT_LEN * G3H * Bsz];
__device__ float2 g_h2[2][(Hd / 2) * Bsz];
__device__ float2 g_hall[(size_t)TGT_LEN * (Hd / 2) * Bsz];
__device__ float2 g_oeall[(size_t)TGT_LEN * (Ed / 2) * Bsz];
__device__ float  g_pm[(size_t)TGT_LEN * NCHB * Bsz];
__device__ float  g_ps[(size_t)TGT_LEN * NCHB * Bsz];
__device__ int    g_pi[(size_t)TGT_LEN * NCHB * Bsz];
__device__ float  g_loss_t[TGT_LEN];
__device__ unsigned g_bar_rec;

// ---------------- f32x2 packed FMA ------------------------------------------
__device__ __forceinline__ float2 ffma2(float2 a, float2 b, float2 c) {
    unsigned long long A = *reinterpret_cast<unsigned long long*>(&a);
    unsigned long long B = *reinterpret_cast<unsigned long long*>(&b);
    unsigned long long C = *reinterpret_cast<unsigned long long*>(&c);
    unsigned long long D;
    asm("fma.rn.f32x2 %0, %1, %2, %3;" : "=l"(D) : "l"(A), "l"(B), "l"(C));
    return *reinterpret_cast<float2*>(&D);
}

// ---------------- grid-wide barrier (single counter — measured best) ---------
__device__ __forceinline__ void grid_bar(unsigned* bar, unsigned& target) {
    __syncthreads();
    if (threadIdx.x == 0) {
        target += NB;
        asm volatile("red.release.gpu.global.add.u32 [%0], %1;"
                     :: "l"(bar), "r"(1u) : "memory");
        unsigned v;
        do {
            asm volatile("ld.acquire.gpu.global.u32 %0, [%1];"
                         : "=r"(v) : "l"(bar) : "memory");
        } while (v < target);
    }
    __syncthreads();
}

__global__ void init_kernel() {
    int i = blockIdx.x * blockDim.x + threadIdx.x;
    if (i < Hd * Bsz) ((float*)g_h2[0])[i] = 0.0f;   // encoder h0 = 0
    if (i == 0) g_bar_rec = 0u;
}

// ---------------- gi precompute (fused enc+dec, 500 blocks) -------------------
__global__ void gi_fused(const int* __restrict__ src,
                         const int* __restrict__ tgt,
                         const float* __restrict__ emb,
                         const float* __restrict__ eWih,
                         const float* __restrict__ ebih,
                         const float* __restrict__ dWih,
                         const float* __restrict__ dbih) {
    __shared__ float2 xs2[(Ed / 2) * Bsz];
    __shared__ int    tk[Bsz];
    const int bid = blockIdx.x, tid = threadIdx.x;
    const int dec_mode = bid >= SRC_LEN;
    const int t = dec_mode ? bid - SRC_LEN : bid;
    const int* toks = dec_mode ? tgt : src;
    const float* Wih = dec_mode ? dWih : eWih;
    const float* bih = dec_mode ? dbih : ebih;

    if (tid < Bsz) {
        int tok;
        if (dec_mode) tok = (t == 0) ? 1 : toks[(t - 1) * Bsz + tid];
        else          tok = toks[t * Bsz + tid];
        tk[tid] = tok;
    }
    __syncthreads();
    {
        const int b = tid & 31, chunk = tid >> 5;
        const float* erow = emb + (size_t)tk[b] * Ed;
        #pragma unroll
        for (int c = 0; c < 8; c++) {
            int e0 = chunk * 32 + c * 4;
            float4 v = *(const float4*)(erow + e0);
            xs2[(e0 >> 1) * Bsz + b]       = make_float2(v.x, v.y);
            xs2[((e0 >> 1) + 1) * Bsz + b] = make_float2(v.z, v.w);
        }
    }
    __syncthreads();

    const int wid = tid >> 5, lane = tid & 31;
    float* out_t = (dec_mode ? g_gi_dec : g_gi_enc) + (size_t)t * G3H * Bsz;

    for (int jt = 0; jt < 24; jt++) {
        const int j0 = wid * 192 + jt * 8;
        float2 acc[8];
        #pragma unroll
        for (int i = 0; i < 8; i++) acc[i] = make_float2(0.f, 0.f);
        #pragma unroll 2
        for (int e = 0; e < Ed; e += 4) {
            const int e2 = e >> 1;
            float2 x01 = xs2[e2 * Bsz + lane];
            float2 x23 = xs2[(e2 + 1) * Bsz + lane];
            const float* wp = Wih + (size_t)j0 * Ed + e;
            #pragma unroll
            for (int jj = 0; jj < 8; jj++) {
                float4 w = *(const float4*)(wp + (size_t)jj * Ed);
                acc[jj] = ffma2(make_float2(w.x, w.y), x01, acc[jj]);
                acc[jj] = ffma2(make_float2(w.z, w.w), x23, acc[jj]);
            }
        }
        #pragma unroll
        for (int jj = 0; jj < 8; jj++)
            out_t[(size_t)(j0 + jj) * Bsz + lane] = acc[jj].x + acc[jj].y + bih[j0 + jj];
    }
}

// ---------------- persistent GRU: 16-way k-split, h direct from L2 -----------
#define WS_F   0
#define PP_F   6144
#define REC_SMEM_BYTES ((6144 + 6144) * 4)

__device__ __forceinline__ void load_ws(float* ws, const float* __restrict__ Whh, int j0) {
    for (int i = threadIdx.x; i < 12 * 128; i += RTHR) {
        int r = i >> 7, k4 = i & 127;
        int g = r >> 2, jl = r & 3;
        ((float4*)ws)[r * 128 + k4] =
            *(const float4*)&Whh[((size_t)(g * Hd + j0 + jl)) * Hd + k4 * 4];
    }
}

// one GRU step. hprev: GLOBAL h layout [k/2][b] float2. hout: global same layout.
__device__ __forceinline__ void hh_step(const float* __restrict__ ws,
                                        const float2* __restrict__ hprev,
                                        const float* __restrict__ gi_t,
                                        const float* __restrict__ bhh,
                                        float2* __restrict__ hout,
                                        float* __restrict__ pp,
                                        int j0) {
    const int tid = threadIdx.x, wid = tid >> 5, lane = tid & 31;

    // epilogue warps prefetch gate inputs + old h early (hidden by k-loop)
    float pg[6];
    float2 hold = make_float2(0.f, 0.f);
    if (wid < 2) {
        const int j = j0 + 2 * wid;
        pg[0] = __ldcg(&gi_t[(size_t)(0 * Hd + j) * Bsz + lane]);
        pg[1] = __ldcg(&gi_t[(size_t)(0 * Hd + j + 1) * Bsz + lane]);
        pg[2] = __ldcg(&gi_t[(size_t)(1 * Hd + j) * Bsz + lane]);
        pg[3] = __ldcg(&gi_t[(size_t)(1 * Hd + j + 1) * Bsz + lane]);
        pg[4] = __ldcg(&gi_t[(size_t)(2 * Hd + j) * Bsz + lane]);
        pg[5] = __ldcg(&gi_t[(size_t)(2 * Hd + j + 1) * Bsz + lane]);
        hold  = __ldcg(&hprev[(j0 / 2 + wid) * Bsz + lane]);
    }

    float2 acc[12];
    #pragma unroll
    for (int i = 0; i < 12; i++) acc[i] = make_float2(0.f, 0.f);

    const int kbeg = wid * 32;                     // each warp: 32-k slice
    #pragma unroll
    for (int k = kbeg; k < kbeg + 32; k += 4) {
        const int k2 = k >> 1;
        float2 x01 = __ldcg(&hprev[k2 * Bsz + lane]);
        float2 x23 = __ldcg(&hprev[(k2 + 1) * Bsz + lane]);
        #pragma unroll
        for (int r = 0; r < 12; r++) {
            float4 w = *(const float4*)&ws[r * Hd + k];
            acc[r] = ffma2(make_float2(w.x, w.y), x01, acc[r]);
            acc[r] = ffma2(make_float2(w.z, w.w), x23, acc[r]);
        }
    }
    #pragma unroll
    for (int r = 0; r < 12; r++)
        pp[(wid * 12 + r) * 32 + lane] = acc[r].x + acc[r].y;
    __syncthreads();

    if (wid < 2) {
        const int e = wid;
        float s[6];
        #pragma unroll
        for (int g = 0; g < 3; g++) {
            #pragma unroll
            for (int jj = 0; jj < 2; jj++) {
                const int row = g * 4 + 2 * e + jj;
                float v = 0.f;
                #pragma unroll
                for (int w = 0; w < 16; w++) v += pp[(w * 12 + row) * 32 + lane];
                s[g * 2 + jj] = v;
            }
        }
        float hn[2];
        #pragma unroll
        for (int jj = 0; jj < 2; jj++) {
            int j = j0 + 2 * e + jj;
            float ghr = s[0 + jj] + bhh[j];
            float ghz = s[2 + jj] + bhh[Hd + j];
            float ghn = s[4 + jj] + bhh[2 * Hd + j];
            float r = 1.0f / (1.0f + expf(-(pg[0 + jj] + ghr)));
            float z = 1.0f / (1.0f + expf(-(pg[2 + jj] + ghz)));
            float n = tanhf(pg[4 + jj] + r * ghn);
            float ho = jj ? hold.y : hold.x;
            hn[jj] = (1.0f - z) * n + z * ho;
        }
        __stcg(&hout[(j0 / 2 + e) * Bsz + lane], make_float2(hn[0], hn[1]));
    }
}

// fused encoder + decoder recurrence (one launch, one barrier counter)
__global__ void __launch_bounds__(RTHR, 1)
rec_persist(const float* __restrict__ eWhh, const float* __restrict__ ebhh,
            const float* __restrict__ dWhh, const float* __restrict__ dbhh) {
    extern __shared__ float sm[];
    float* ws = sm + WS_F;
    float* pp = sm + PP_F;
    const int j0 = blockIdx.x * 4;

    load_ws(ws, eWhh, j0);
    __syncthreads();

    unsigned tgt = 0;
    for (int t = 0; t < SRC_LEN; t++) {
        const float2* hprev = g_h2[t & 1];
        float2* hnew = g_h2[(t & 1) ^ 1];
        hh_step(ws, hprev, g_gi_enc + (size_t)t * G3H * Bsz, ebhh, hnew, pp, j0);
        grid_bar(&g_bar_rec, tgt);
    }
    // SRC_LEN=400 even -> encoder final h in g_h2[0]

    load_ws(ws, dWhh, j0);      // per-block smem: safe after local barrier
    __syncthreads();

    for (int t = 0; t < TGT_LEN; t++) {
        const float2* hprev = (t == 0) ? g_h2[0]
                                       : &g_hall[(size_t)(t - 1) * (Hd / 2) * Bsz];
        hh_step(ws, hprev, g_gi_dec + (size_t)t * G3H * Bsz, dbhh,
                &g_hall[(size_t)t * (Hd / 2) * Bsz], pp, j0);
        grid_bar(&g_bar_rec, tgt);
    }
}

// ---------------- decoder phase B: batched pre (oe_all) -----------------------
__global__ void __launch_bounds__(256)
pre_all(const float* __restrict__ preW, const float* __restrict__ preb) {
    extern __shared__ float sm[];
    float2* hs = (float2*)sm;     // 64KB
    const int t = blockIdx.x, tid = threadIdx.x;
    {
        const float4* s4 = (const float4*)&g_hall[(size_t)t * (Hd / 2) * Bsz];
        float4* d4 = (float4*)hs;
        for (int i = tid; i < (Hd * Bsz) / 4; i += 256) d4[i] = __ldg(s4 + i);
        __syncthreads();
    }
    const int wid = tid >> 5, lane = tid & 31;
    for (int grp = 0; grp < 4; grp++) {
        const int e0 = wid * 32 + grp * 8;
        float2 acc[8];
        #pragma unroll
        for (int i = 0; i < 8; i++) acc[i] = make_float2(0.f, 0.f);
        const float* wp = preW + (size_t)e0 * Hd;
        #pragma unroll 2
        for (int k = 0; k < Hd; k += 4) {
            const int k2 = k >> 1;
            float2 x01 = hs[k2 * Bsz + lane];
            float2 x23 = hs[(k2 + 1) * Bsz + lane];
            #pragma unroll
            for (int r = 0; r < 8; r++) {
                float4 w = *(const float4*)(wp + (size_t)r * Hd + k);
                acc[r] = ffma2(make_float2(w.x, w.y), x01, acc[r]);
                acc[r] = ffma2(make_float2(w.z, w.w), x23, acc[r]);
            }
        }
        #pragma unroll
        for (int i = 0; i < 4; i++) {
            float v0 = acc[2 * i].x     + acc[2 * i].y     + preb[e0 + 2 * i];
            float v1 = acc[2 * i + 1].x + acc[2 * i + 1].y + preb[e0 + 2 * i + 1];
            g_oeall[((size_t)t * (Ed / 2) + (e0 >> 1) + i) * Bsz + lane] =
                make_float2(v0, v1);
        }
    }
}

// ---------------- decoder phase C: batched logits, 512 thr, 512-v chunks ------
#define LG_SMEM_F (4 * (Ed / 2) * Bsz * 2 + 3 * (TQ * 16 * 32))
__global__ void __launch_bounds__(512, 1)
logits_all(const float* __restrict__ emb, const float* __restrict__ outb) {
    extern __shared__ float sm[];
    float2* oes = (float2*)sm;                       // [4][(Ed/2)*Bsz]
    float*  mm  = sm + 4 * (Ed / 2) * Bsz * 2;       // [TQ][16][32]
    float*  ms  = mm + TQ * 16 * 32;
    int*    mi  = (int*)(ms + TQ * 16 * 32);

    const int bid = blockIdx.x;
    const int c = bid / TGROUPS, grp = bid % TGROUPS;
    const int t0 = grp * TQ;
    const int tid = threadIdx.x, wid = tid >> 5, lane = tid & 31;

    {   // stage 4 timesteps of out_emb
        const float4* s4 = (const float4*)&g_oeall[(size_t)t0 * (Ed / 2) * Bsz];
        float4* d4 = (float4*)oes;
        for (int i = tid; i < 4 * (Ed * Bsz) / 4; i += 512) d4[i] = __ldg(s4 + i);
        __syncthreads();
    }

    const int base = c * LCH + wid * 32;
    float m[TQ], s[TQ]; int bi[TQ];
    #pragma unroll
    for (int t = 0; t < TQ; t++) { m[t] = -INFINITY; s[t] = 0.f; bi[t] = 0; }

    for (int vt = 0; vt < 4; vt++) {
        const int vb = base + vt * 8;
        if (vb >= Vd) break;                         // last chunk upper warps idle
        float2 acc[TQ][8];
        #pragma unroll
        for (int t = 0; t < TQ; t++)
            #pragma unroll
            for (int i = 0; i < 8; i++) acc[t][i] = make_float2(0.f, 0.f);
        const float* ep = emb + (size_t)vb * Ed;

        for (int e = 0; e < Ed; e += 4) {
            const int e2 = e >> 1;
            float2 x01[TQ], x23[TQ];
            #pragma unroll
            for (int t = 0; t < TQ; t++) {
                x01[t] = oes[t * (Ed / 2) * Bsz + e2 * Bsz + lane];
                x23[t] = oes[t * (Ed / 2) * Bsz + (e2 + 1) * Bsz + lane];
            }
            #pragma unroll
            for (int vv = 0; vv < 8; vv++) {
                float4 w = *(const float4*)(ep + (size_t)vv * Ed + e);
                float2 w01 = make_float2(w.x, w.y), w23 = make_float2(w.z, w.w);
                #pragma unroll
                for (int t = 0; t < TQ; t++) {
                    acc[t][vv] = ffma2(w01, x01[t], acc[t][vv]);
                    acc[t][vv] = ffma2(w23, x23[t], acc[t][vv]);
                }
            }
        }
        #pragma unroll
        for (int vv = 0; vv < 8; vv++) {
            float lb = outb[vb + vv];
            #pragma unroll
            for (int t = 0; t < TQ; t++) {
                float l = acc[t][vv].x + acc[t][vv].y + lb;
                if (l > m[t]) { s[t] = s[t] * __expf(m[t] - l) + 1.0f; m[t] = l; bi[t] = vb + vv; }
                else          { s[t] += __expf(l - m[t]); }
            }
        }
    }
    #pragma unroll
    for (int t = 0; t < TQ; t++) {
        mm[(t * 16 + wid) * 32 + lane] = m[t];
        ms[(t * 16 + wid) * 32 + lane] = s[t];
        mi[(t * 16 + wid) * 32 + lane] = bi[t];
    }
    __syncthreads();

    if (wid < TQ) {
        const int tt = wid;
        float M = mm[(tt * 16 + 0) * 32 + lane];
        float S = ms[(tt * 16 + 0) * 32 + lane];
        int   I = mi[(tt * 16 + 0) * 32 + lane];
        #pragma unroll
        for (int w = 1; w < 16; w++) {               // ascending v order
            float m2 = mm[(tt * 16 + w) * 32 + lane];
            float s2 = ms[(tt * 16 + w) * 32 + lane];
            int   i2 = mi[(tt * 16 + w) * 32 + lane];
            if (m2 > M) { S = S * __expf(M - m2) + s2; I = i2; M = m2; }
            else        { S += s2 * __expf(m2 - M); } // -INF partial: +0, exact no-op
        }
        const size_t idx = ((size_t)(t0 + tt) * NCHB + c) * 32 + lane;
        g_pm[idx] = M; g_ps[idx] = S; g_pi[idx] = I;
    }
}

// ---------------- decoder phase D: per-t merge, tokens, loss ------------------
__global__ void __launch_bounds__(256)
merge_all(const int* __restrict__ tgt, const float* __restrict__ emb,
          const float* __restrict__ outb, float* __restrict__ dout) {
    __shared__ float smm[8 * 32], sms[8 * 32];
    __shared__ int   smi[8 * 32];
    const int t = blockIdx.x, tid = threadIdx.x, b = tid & 31, cg = tid >> 5;

    float m = -INFINITY, s = 0.f; int bi = 0;
    const int cb = cg * 8, ce = (cb + 8 < NCHB) ? cb + 8 : NCHB;
    for (int c = cb; c < ce; c++) {                  // ascending v order
        const size_t idx = ((size_t)t * NCHB + c) * 32 + b;
        float m2 = g_pm[idx], s2 = g_ps[idx];
        int   i2 = g_pi[idx];
        if (m2 > m) { s = s * __expf(m - m2) + s2; bi = i2; m = m2; }
        else        { s += s2 * __expf(m2 - m); }
    }
    smm[cg * 32 + b] = m; sms[cg * 32 + b] = s; smi[cg * 32 + b] = bi;
    __syncthreads();

    if (tid < 32) {
        m = smm[tid]; s = sms[tid]; bi = smi[tid];
        #pragma unroll
        for (int c2 = 1; c2 < 8; c2++) {
            float m2 = smm[c2 * 32 + tid];
            float s2 = sms[c2 * 32 + tid];
            int   i2 = smi[c2 * 32 + tid];
            if (m2 > m) { s = s * __expf(m - m2) + s2; bi = i2; m = m2; }
            else        { s += s2 * __expf(m2 - m); }
        }
        int gold = tgt[t * Bsz + tid];
        float2 acc = make_float2(0.f, 0.f);
        const float* grow = emb + (size_t)gold * Ed;
        #pragma unroll 4
        for (int e = 0; e < Ed; e += 4) {
            float4 w = *(const float4*)(grow + e);
            float2 o01 = g_oeall[((size_t)t * (Ed / 2) + (e >> 1)) * Bsz + tid];
            float2 o23 = g_oeall[((size_t)t * (Ed / 2) + (e >> 1) + 1) * Bsz + tid];
            acc = ffma2(make_float2(w.x, w.y), o01, acc);
            acc = ffma2(make_float2(w.z, w.w), o23, acc);
        }
        float lg = acc.x + acc.y + outb[gold];
        float prob = expf(lg - m) / s;
        float nll = -logf(prob + 1e-20f);
        float maskf = (gold != 0) ? 1.0f : 0.0f;
        float num = nll * maskf, den = maskf;
        #pragma unroll
        for (int o = 16; o > 0; o >>= 1) {
            num += __shfl_down_sync(0xffffffffu, num, o);
            den += __shfl_down_sync(0xffffffffu, den, o);
        }
        dout[t * Bsz + tid] = (float)bi;
        if (tid == 0) g_loss_t[t] = num / fmaxf(den, 1.0f);
    }
}

__global__ void loss_fin(float* __restrict__ dout, int out_size) {
    if (out_size <= TGT_LEN * Bsz) return;
    const int lane = threadIdx.x;
    float s = 0.f;
    for (int t = lane; t < TGT_LEN; t += 32) s += g_loss_t[t];
    #pragma unroll
    for (int o = 16; o > 0; o >>= 1) s += __shfl_down_sync(0xffffffffu, s, o);
    if (lane == 0) dout[TGT_LEN * Bsz] = s;
}

// ---------------- launch ------------------------------------------------------
extern "C" void kernel_launch(void* const* d_in, const int* in_sizes, int n_in,
                              void* d_out, int out_size) {
    const int*   src  = (const int*)  d_in[0];
    const int*   tgt  = (const int*)  d_in[1];
    const float* emb  = (const float*)d_in[2];
    const float* eWih = (const float*)d_in[3];
    const float* eWhh = (const float*)d_in[4];
    const float* ebih = (const float*)d_in[5];
    const float* ebhh = (const float*)d_in[6];
    const float* dWih = (const float*)d_in[7];
    const float* dWhh = (const float*)d_in[8];
    const float* dbih = (const float*)d_in[9];
    const float* dbhh = (const float*)d_in[10];
    const float* preW = (const float*)d_in[11];
    const float* preb = (const float*)d_in[12];
    const float* outb = (const float*)d_in[13];
    float* out = (float*)d_out;

    static int attr_done = 0;
    if (!attr_done) {
        cudaFuncSetAttribute(rec_persist, cudaFuncAttributeMaxDynamicSharedMemorySize,
                             REC_SMEM_BYTES);
        cudaFuncSetAttribute(pre_all, cudaFuncAttributeMaxDynamicSharedMemorySize,
                             65536);
        cudaFuncSetAttribute(logits_all, cudaFuncAttributeMaxDynamicSharedMemorySize,
                             LG_SMEM_F * 4);
        attr_done = 1;
    }

    init_kernel<<<64, 256>>>();
    gi_fused<<<SRC_LEN + TGT_LEN, 256>>>(src, tgt, emb, eWih, ebih, dWih, dbih);
    rec_persist<<<NB, RTHR, REC_SMEM_BYTES>>>(eWhh, ebhh, dWhh, dbhh);
    pre_all<<<TGT_LEN, 256, 65536>>>(preW, preb);
    logits_all<<<NCHB * TGROUPS, 512, LG_SMEM_F * 4>>>(emb, outb);
    merge_all<<<TGT_LEN, 256>>>(tgt, emb, outb, out);
    loss_fin<<<1, 32>>>(out, out_size);
}

// round 14
// speedup vs baseline: 1.3561x; 1.0441x over previous
#include <cuda_runtime.h>
#include <math.h>

#define SRC_LEN 400
#define TGT_LEN 100
#define Bsz     32
#define Ed      256
#define Hd      512
#define Vd      32000
#define G3H     1536
#define NB      128      // recurrence blocks (persistent, <=148 SMs)
#define TQ      4        // timesteps per logits block
#define TGROUPS (TGT_LEN / TQ)   // 25
#define LCH     512      // v per logits block (16 warps x 32)
#define NCHB    63       // ceil(32000/512)
#define RTHR    512

// ---------------- device scratch --------------------------------------------
__device__ float  g_gi_enc[(size_t)SRC_LEN * G3H * Bsz];
__device__ float  g_gi_dec[(size_t)TGT_LEN * G3H * Bsz];
__device__ float2 g_h2[2][(Hd / 2) * Bsz];
__device__ float2 g_hall[(size_t)TGT_LEN * (Hd / 2) * Bsz];
__device__ float2 g_oeall[(size_t)TGT_LEN * (Ed / 2) * Bsz];
__device__ float  g_pm[(size_t)TGT_LEN * NCHB * Bsz];
__device__ float  g_ps[(size_t)TGT_LEN * NCHB * Bsz];
__device__ int    g_pi[(size_t)TGT_LEN * NCHB * Bsz];
__device__ float  g_loss_t[TGT_LEN];
__device__ unsigned g_flag[NB * 32];     // per-block completed-epoch, 128B apart

// ---------------- f32x2 packed FMA ------------------------------------------
__device__ __forceinline__ float2 ffma2(float2 a, float2 b, float2 c) {
    unsigned long long A = *reinterpret_cast<unsigned long long*>(&a);
    unsigned long long B = *reinterpret_cast<unsigned long long*>(&b);
    unsigned long long C = *reinterpret_cast<unsigned long long*>(&c);
    unsigned long long D;
    asm("fma.rn.f32x2 %0, %1, %2, %3;" : "=l"(D) : "l"(A), "l"(B), "l"(C));
    return *reinterpret_cast<float2*>(&D);
}

__global__ void init_kernel() {
    int i = blockIdx.x * blockDim.x + threadIdx.x;
    if (i < Hd * Bsz) ((float*)g_h2[0])[i] = 0.0f;   // encoder h0 = 0
    if (i < NB * 32) g_flag[i] = 0u;
}

// ---------------- gi precompute (fused enc+dec, 500 blocks) -------------------
__global__ void gi_fused(const int* __restrict__ src,
                         const int* __restrict__ tgt,
                         const float* __restrict__ emb,
                         const float* __restrict__ eWih,
                         const float* __restrict__ ebih,
                         const float* __restrict__ dWih,
                         const float* __restrict__ dbih) {
    __shared__ float2 xs2[(Ed / 2) * Bsz];
    __shared__ int    tk[Bsz];
    const int bid = blockIdx.x, tid = threadIdx.x;
    const int dec_mode = bid >= SRC_LEN;
    const int t = dec_mode ? bid - SRC_LEN : bid;
    const int* toks = dec_mode ? tgt : src;
    const float* Wih = dec_mode ? dWih : eWih;
    const float* bih = dec_mode ? dbih : ebih;

    if (tid < Bsz) {
        int tok;
        if (dec_mode) tok = (t == 0) ? 1 : toks[(t - 1) * Bsz + tid];
        else          tok = toks[t * Bsz + tid];
        tk[tid] = tok;
    }
    __syncthreads();
    {
        const int b = tid & 31, chunk = tid >> 5;
        const float* erow = emb + (size_t)tk[b] * Ed;
        #pragma unroll
        for (int c = 0; c < 8; c++) {
            int e0 = chunk * 32 + c * 4;
            float4 v = *(const float4*)(erow + e0);
            xs2[(e0 >> 1) * Bsz + b]       = make_float2(v.x, v.y);
            xs2[((e0 >> 1) + 1) * Bsz + b] = make_float2(v.z, v.w);
        }
    }
    __syncthreads();

    const int wid = tid >> 5, lane = tid & 31;
    float* out_t = (dec_mode ? g_gi_dec : g_gi_enc) + (size_t)t * G3H * Bsz;

    for (int jt = 0; jt < 24; jt++) {
        const int j0 = wid * 192 + jt * 8;
        float2 acc[8];
        #pragma unroll
        for (int i = 0; i < 8; i++) acc[i] = make_float2(0.f, 0.f);
        #pragma unroll 2
        for (int e = 0; e < Ed; e += 4) {
            const int e2 = e >> 1;
            float2 x01 = xs2[e2 * Bsz + lane];
            float2 x23 = xs2[(e2 + 1) * Bsz + lane];
            const float* wp = Wih + (size_t)j0 * Ed + e;
            #pragma unroll
            for (int jj = 0; jj < 8; jj++) {
                float4 w = *(const float4*)(wp + (size_t)jj * Ed);
                acc[jj] = ffma2(make_float2(w.x, w.y), x01, acc[jj]);
                acc[jj] = ffma2(make_float2(w.z, w.w), x23, acc[jj]);
            }
        }
        #pragma unroll
        for (int jj = 0; jj < 8; jj++)
            out_t[(size_t)(j0 + jj) * Bsz + lane] = acc[jj].x + acc[jj].y + bih[j0 + jj];
    }
}

// ---------------- dataflow persistent GRU ------------------------------------
// smem: ws[12][512] (24KB) + pp[2][16*12*32] (48KB) = 72KB
#define WS_F   0
#define PP0_F  6144
#define PP1_F  (6144 + 6144)
#define REC_SMEM_BYTES ((6144 + 2 * 6144) * 4)

__device__ __forceinline__ void load_ws(float* ws, const float* __restrict__ Whh, int j0) {
    for (int i = threadIdx.x; i < 12 * 128; i += RTHR) {
        int r = i >> 7, k4 = i & 127;
        int g = r >> 2, jl = r & 3;
        ((float4*)ws)[r * 128 + k4] =
            *(const float4*)&Whh[((size_t)(g * Hd + j0 + jl)) * Hd + k4 * 4];
    }
}

// warp w consumes h rows produced by blocks 8w..8w+7: lanes 0-7 poll in parallel
__device__ __forceinline__ void poll_producers(int wid, int lane, unsigned need) {
    if (lane < 8) {
        const unsigned* p = &g_flag[(wid * 8 + lane) * 32];
        unsigned v;
        do {
            asm volatile("ld.acquire.gpu.global.u32 %0, [%1];"
                         : "=r"(v) : "l"(p) : "memory");
        } while (v < need);
    }
    __syncwarp();
}

// one dataflow GRU step; epoch >= 1. hprev/hout global [k/2][b] float2.
__device__ __forceinline__ void df_step(const float* __restrict__ ws,
                                        const float2* __restrict__ hprev,
                                        const float* __restrict__ gi_t,
                                        const float* __restrict__ bhh,
                                        float2* __restrict__ hout,
                                        float* __restrict__ pp0,
                                        float* __restrict__ pp1,
                                        int j0, unsigned epoch) {
    const int tid = threadIdx.x, wid = tid >> 5, lane = tid & 31;
    float* pp = (epoch & 1u) ? pp1 : pp0;

    // wait for this warp's 8 producers to publish h_{epoch-1}
    poll_producers(wid, lane, epoch - 1u);

    // epilogue warps prefetch gate inputs + own old h (own rows: written by
    // this block's warps 0-1 last step — program-order safe)
    float pg[6];
    float2 hold = make_float2(0.f, 0.f);
    if (wid < 2) {
        const int j = j0 + 2 * wid;
        pg[0] = __ldcg(&gi_t[(size_t)(0 * Hd + j) * Bsz + lane]);
        pg[1] = __ldcg(&gi_t[(size_t)(0 * Hd + j + 1) * Bsz + lane]);
        pg[2] = __ldcg(&gi_t[(size_t)(1 * Hd + j) * Bsz + lane]);
        pg[3] = __ldcg(&gi_t[(size_t)(1 * Hd + j + 1) * Bsz + lane]);
        pg[4] = __ldcg(&gi_t[(size_t)(2 * Hd + j) * Bsz + lane]);
        pg[5] = __ldcg(&gi_t[(size_t)(2 * Hd + j + 1) * Bsz + lane]);
        hold  = __ldcg(&hprev[(j0 / 2 + wid) * Bsz + lane]);
    }

    float2 acc[12];
    #pragma unroll
    for (int i = 0; i < 12; i++) acc[i] = make_float2(0.f, 0.f);

    const int kbeg = wid * 32;
    #pragma unroll
    for (int k = kbeg; k < kbeg + 32; k += 4) {
        const int k2 = k >> 1;
        float2 x01 = __ldcg(&hprev[k2 * Bsz + lane]);
        float2 x23 = __ldcg(&hprev[(k2 + 1) * Bsz + lane]);
        #pragma unroll
        for (int r = 0; r < 12; r++) {
            float4 w = *(const float4*)&ws[r * Hd + k];
            acc[r] = ffma2(make_float2(w.x, w.y), x01, acc[r]);
            acc[r] = ffma2(make_float2(w.z, w.w), x23, acc[r]);
        }
    }
    #pragma unroll
    for (int r = 0; r < 12; r++)
        pp[(wid * 12 + r) * 32 + lane] = acc[r].x + acc[r].y;
    __syncthreads();   // all warps acquired + partials ready (gates the h write)

    if (wid < 2) {
        const int e = wid;
        float s[6];
        #pragma unroll
        for (int g = 0; g < 3; g++) {
            #pragma unroll
            for (int jj = 0; jj < 2; jj++) {
                const int row = g * 4 + 2 * e + jj;
                float v = 0.f;
                #pragma unroll
                for (int w = 0; w < 16; w++) v += pp[(w * 12 + row) * 32 + lane];
                s[g * 2 + jj] = v;
            }
        }
        float hn[2];
        #pragma unroll
        for (int jj = 0; jj < 2; jj++) {
            int j = j0 + 2 * e + jj;
            float ghr = s[0 + jj] + bhh[j];
            float ghz = s[2 + jj] + bhh[Hd + j];
            float ghn = s[4 + jj] + bhh[2 * Hd + j];
            float r = 1.0f / (1.0f + expf(-(pg[0 + jj] + ghr)));
            float z = 1.0f / (1.0f + expf(-(pg[2 + jj] + ghz)));
            float n = tanhf(pg[4 + jj] + r * ghn);
            float ho = jj ? hold.y : hold.x;
            hn[jj] = (1.0f - z) * n + z * ho;
        }
        __stcg(&hout[(j0 / 2 + e) * Bsz + lane], make_float2(hn[0], hn[1]));
        asm volatile("bar.sync 1, 64;" ::: "memory");   // both epilogue warps done
        if (tid == 0)
            asm volatile("st.release.gpu.global.u32 [%0], %1;"
                         :: "l"(&g_flag[blockIdx.x * 32]), "r"(epoch) : "memory");
    }
    // warps 2-15 proceed immediately to next step's poll (pp parity-safe)
}

__global__ void __launch_bounds__(RTHR, 1)
rec_persist(const float* __restrict__ eWhh, const float* __restrict__ ebhh,
            const float* __restrict__ dWhh, const float* __restrict__ dbhh) {
    extern __shared__ float sm[];
    float* ws  = sm + WS_F;
    float* pp0 = sm + PP0_F;
    float* pp1 = sm + PP1_F;
    const int j0 = blockIdx.x * 4;

    load_ws(ws, eWhh, j0);
    __syncthreads();

    // encoder: epochs 1..400
    for (int t = 0; t < SRC_LEN; t++) {
        df_step(ws, g_h2[t & 1], g_gi_enc + (size_t)t * G3H * Bsz, ebhh,
                g_h2[(t & 1) ^ 1], pp0, pp1, j0, (unsigned)(t + 1));
    }
    // encoder final h in g_h2[0]

    __syncthreads();                 // all warps past encoder k-loops
    load_ws(ws, dWhh, j0);
    __syncthreads();

    // decoder: epochs 401..500 (g_hall is per-t storage, no ring hazard)
    for (int t = 0; t < TGT_LEN; t++) {
        const float2* hprev = (t == 0) ? g_h2[0]
                                       : &g_hall[(size_t)(t - 1) * (Hd / 2) * Bsz];
        df_step(ws, hprev, g_gi_dec + (size_t)t * G3H * Bsz, dbhh,
                &g_hall[(size_t)t * (Hd / 2) * Bsz], pp0, pp1, j0,
                (unsigned)(SRC_LEN + t + 1));
    }
}

// ---------------- decoder phase B: batched pre, 4 e-quarters per t ------------
__global__ void __launch_bounds__(256)
pre_all(const float* __restrict__ preW, const float* __restrict__ preb) {
    extern __shared__ float sm[];
    float2* hs = (float2*)sm;     // 64KB
    const int t = blockIdx.x >> 2, q = blockIdx.x & 3;
    const int tid = threadIdx.x;
    {
        const float4* s4 = (const float4*)&g_hall[(size_t)t * (Hd / 2) * Bsz];
        float4* d4 = (float4*)hs;
        for (int i = tid; i < (Hd * Bsz) / 4; i += 256) d4[i] = __ldg(s4 + i);
        __syncthreads();
    }
    const int wid = tid >> 5, lane = tid & 31;
    const int e0 = q * 64 + wid * 8;          // each warp: 8 e-rows
    float2 acc[8];
    #pragma unroll
    for (int i = 0; i < 8; i++) acc[i] = make_float2(0.f, 0.f);
    const float* wp = preW + (size_t)e0 * Hd;
    #pragma unroll 2
    for (int k = 0; k < Hd; k += 4) {
        const int k2 = k >> 1;
        float2 x01 = hs[k2 * Bsz + lane];
        float2 x23 = hs[(k2 + 1) * Bsz + lane];
        #pragma unroll
        for (int r = 0; r < 8; r++) {
            float4 w = *(const float4*)(wp + (size_t)r * Hd + k);
            acc[r] = ffma2(make_float2(w.x, w.y), x01, acc[r]);
            acc[r] = ffma2(make_float2(w.z, w.w), x23, acc[r]);
        }
    }
    #pragma unroll
    for (int i = 0; i < 4; i++) {
        float v0 = acc[2 * i].x     + acc[2 * i].y     + preb[e0 + 2 * i];
        float v1 = acc[2 * i + 1].x + acc[2 * i + 1].y + preb[e0 + 2 * i + 1];
        g_oeall[((size_t)t * (Ed / 2) + (e0 >> 1) + i) * Bsz + lane] =
            make_float2(v0, v1);
    }
}

// ---------------- decoder phase C: batched logits, 512 thr, 512-v chunks ------
#define LG_SMEM_F (4 * (Ed / 2) * Bsz * 2 + 3 * (TQ * 16 * 32))
__global__ void __launch_bounds__(512, 1)
logits_all(const float* __restrict__ emb, const float* __restrict__ outb) {
    extern __shared__ float sm[];
    float2* oes = (float2*)sm;
    float*  mm  = sm + 4 * (Ed / 2) * Bsz * 2;
    float*  ms  = mm + TQ * 16 * 32;
    int*    mi  = (int*)(ms + TQ * 16 * 32);

    const int bid = blockIdx.x;
    const int c = bid / TGROUPS, grp = bid % TGROUPS;
    const int t0 = grp * TQ;
    const int tid = threadIdx.x, wid = tid >> 5, lane = tid & 31;

    {
        const float4* s4 = (const float4*)&g_oeall[(size_t)t0 * (Ed / 2) * Bsz];
        float4* d4 = (float4*)oes;
        for (int i = tid; i < 4 * (Ed * Bsz) / 4; i += 512) d4[i] = __ldg(s4 + i);
        __syncthreads();
    }

    const int base = c * LCH + wid * 32;
    float m[TQ], s[TQ]; int bi[TQ];
    #pragma unroll
    for (int t = 0; t < TQ; t++) { m[t] = -INFINITY; s[t] = 0.f; bi[t] = 0; }

    for (int vt = 0; vt < 4; vt++) {
        const int vb = base + vt * 8;
        if (vb >= Vd) break;
        float2 acc[TQ][8];
        #pragma unroll
        for (int t = 0; t < TQ; t++)
            #pragma unroll
            for (int i = 0; i < 8; i++) acc[t][i] = make_float2(0.f, 0.f);
        const float* ep = emb + (size_t)vb * Ed;

        for (int e = 0; e < Ed; e += 4) {
            const int e2 = e >> 1;
            float2 x01[TQ], x23[TQ];
            #pragma unroll
            for (int t = 0; t < TQ; t++) {
                x01[t] = oes[t * (Ed / 2) * Bsz + e2 * Bsz + lane];
                x23[t] = oes[t * (Ed / 2) * Bsz + (e2 + 1) * Bsz + lane];
            }
            #pragma unroll
            for (int vv = 0; vv < 8; vv++) {
                float4 w = *(const float4*)(ep + (size_t)vv * Ed + e);
                float2 w01 = make_float2(w.x, w.y), w23 = make_float2(w.z, w.w);
                #pragma unroll
                for (int t = 0; t < TQ; t++) {
                    acc[t][vv] = ffma2(w01, x01[t], acc[t][vv]);
                    acc[t][vv] = ffma2(w23, x23[t], acc[t][vv]);
                }
            }
        }
        #pragma unroll
        for (int vv = 0; vv < 8; vv++) {
            float lb = outb[vb + vv];
            #pragma unroll
            for (int t = 0; t < TQ; t++) {
                float l = acc[t][vv].x + acc[t][vv].y + lb;
                if (l > m[t]) { s[t] = s[t] * __expf(m[t] - l) + 1.0f; m[t] = l; bi[t] = vb + vv; }
                else          { s[t] += __expf(l - m[t]); }
            }
        }
    }
    #pragma unroll
    for (int t = 0; t < TQ; t++) {
        mm[(t * 16 + wid) * 32 + lane] = m[t];
        ms[(t * 16 + wid) * 32 + lane] = s[t];
        mi[(t * 16 + wid) * 32 + lane] = bi[t];
    }
    __syncthreads();

    if (wid < TQ) {
        const int tt = wid;
        float M = mm[(tt * 16 + 0) * 32 + lane];
        float S = ms[(tt * 16 + 0) * 32 + lane];
        int   I = mi[(tt * 16 + 0) * 32 + lane];
        #pragma unroll
        for (int w = 1; w < 16; w++) {
            float m2 = mm[(tt * 16 + w) * 32 + lane];
            float s2 = ms[(tt * 16 + w) * 32 + lane];
            int   i2 = mi[(tt * 16 + w) * 32 + lane];
            if (m2 > M) { S = S * __expf(M - m2) + s2; I = i2; M = m2; }
            else        { S += s2 * __expf(m2 - M); }
        }
        const size_t idx = ((size_t)(t0 + tt) * NCHB + c) * 32 + lane;
        g_pm[idx] = M; g_ps[idx] = S; g_pi[idx] = I;
    }
}

// ---------------- decoder phase D: per-t merge, tokens, loss ------------------
__global__ void __launch_bounds__(256)
merge_all(const int* __restrict__ tgt, const float* __restrict__ emb,
          const float* __restrict__ outb, float* __restrict__ dout) {
    __shared__ float smm[8 * 32], sms[8 * 32];
    __shared__ int   smi[8 * 32];
    const int t = blockIdx.x, tid = threadIdx.x, b = tid & 31, cg = tid >> 5;

    float m = -INFINITY, s = 0.f; int bi = 0;
    const int cb = cg * 8, ce = (cb + 8 < NCHB) ? cb + 8 : NCHB;
    for (int c = cb; c < ce; c++) {
        const size_t idx = ((size_t)t * NCHB + c) * 32 + b;
        float m2 = g_pm[idx], s2 = g_ps[idx];
        int   i2 = g_pi[idx];
        if (m2 > m) { s = s * __expf(m - m2) + s2; bi = i2; m = m2; }
        else        { s += s2 * __expf(m2 - m); }
    }
    smm[cg * 32 + b] = m; sms[cg * 32 + b] = s; smi[cg * 32 + b] = bi;
    __syncthreads();

    if (tid < 32) {
        m = smm[tid]; s = sms[tid]; bi = smi[tid];
        #pragma unroll
        for (int c2 = 1; c2 < 8; c2++) {
            float m2 = smm[c2 * 32 + tid];
            float s2 = sms[c2 * 32 + tid];
            int   i2 = smi[c2 * 32 + tid];
            if (m2 > m) { s = s * __expf(m - m2) + s2; bi = i2; m = m2; }
            else        { s += s2 * __expf(m2 - m); }
        }
        int gold = tgt[t * Bsz + tid];
        float2 acc = make_float2(0.f, 0.f);
        const float* grow = emb + (size_t)gold * Ed;
        #pragma unroll 4
        for (int e = 0; e < Ed; e += 4) {
            float4 w = *(const float4*)(grow + e);
            float2 o01 = g_oeall[((size_t)t * (Ed / 2) + (e >> 1)) * Bsz + tid];
            float2 o23 = g_oeall[((size_t)t * (Ed / 2) + (e >> 1) + 1) * Bsz + tid];
            acc = ffma2(make_float2(w.x, w.y), o01, acc);
            acc = ffma2(make_float2(w.z, w.w), o23, acc);
        }
        float lg = acc.x + acc.y + outb[gold];
        float prob = expf(lg - m) / s;
        float nll = -logf(prob + 1e-20f);
        float maskf = (gold != 0) ? 1.0f : 0.0f;
        float num = nll * maskf, den = maskf;
        #pragma unroll
        for (int o = 16; o > 0; o >>= 1) {
            num += __shfl_down_sync(0xffffffffu, num, o);
            den += __shfl_down_sync(0xffffffffu, den, o);
        }
        dout[t * Bsz + tid] = (float)bi;
        if (tid == 0) g_loss_t[t] = num / fmaxf(den, 1.0f);
    }
}

__global__ void loss_fin(float* __restrict__ dout, int out_size) {
    if (out_size <= TGT_LEN * Bsz) return;
    const int lane = threadIdx.x;
    float s = 0.f;
    for (int t = lane; t < TGT_LEN; t += 32) s += g_loss_t[t];
    #pragma unroll
    for (int o = 16; o > 0; o >>= 1) s += __shfl_down_sync(0xffffffffu, s, o);
    if (lane == 0) dout[TGT_LEN * Bsz] = s;
}

// ---------------- launch ------------------------------------------------------
extern "C" void kernel_launch(void* const* d_in, const int* in_sizes, int n_in,
                              void* d_out, int out_size) {
    const int*   src  = (const int*)  d_in[0];
    const int*   tgt  = (const int*)  d_in[1];
    const float* emb  = (const float*)d_in[2];
    const float* eWih = (const float*)d_in[3];
    const float* eWhh = (const float*)d_in[4];
    const float* ebih = (const float*)d_in[5];
    const float* ebhh = (const float*)d_in[6];
    const float* dWih = (const float*)d_in[7];
    const float* dWhh = (const float*)d_in[8];
    const float* dbih = (const float*)d_in[9];
    const float* dbhh = (const float*)d_in[10];
    const float* preW = (const float*)d_in[11];
    const float* preb = (const float*)d_in[12];
    const float* outb = (const float*)d_in[13];
    float* out = (float*)d_out;

    static int attr_done = 0;
    if (!attr_done) {
        cudaFuncSetAttribute(rec_persist, cudaFuncAttributeMaxDynamicSharedMemorySize,
                             REC_SMEM_BYTES);
        cudaFuncSetAttribute(pre_all, cudaFuncAttributeMaxDynamicSharedMemorySize,
                             65536);
        cudaFuncSetAttribute(logits_all, cudaFuncAttributeMaxDynamicSharedMemorySize,
                             LG_SMEM_F * 4);
        attr_done = 1;
    }

    init_kernel<<<64, 256>>>();
    gi_fused<<<SRC_LEN + TGT_LEN, 256>>>(src, tgt, emb, eWih, ebih, dWih, dbih);
    rec_persist<<<NB, RTHR, REC_SMEM_BYTES>>>(eWhh, ebhh, dWhh, dbhh);
    pre_all<<<TGT_LEN * 4, 256, 65536>>>(preW, preb);
    logits_all<<<NCHB * TGROUPS, 512, LG_SMEM_F * 4>>>(emb, outb);
    merge_all<<<TGT_LEN, 256>>>(tgt, emb, outb, out);
    loss_fin<<<1, 32>>>(out, out_size);
}